// round 4
// baseline (speedup 1.0000x reference)
#include <cuda_runtime.h>
#include <cuda_bf16.h>
#include <math.h>

#define B_ROWS    8192
#define D_DIM     256
#define N_CLASSES 512
#define ALPHA     0.1
#define R_REP     4
#define SLOTS     (N_CLASSES * (D_DIM / 4))     // 32768 float4 slots per replica

// Scratch (zero-initialized at load; every kernel re-zeroes what it consumed,
// so graph replays always start clean).
__device__ float4       g_cs4[R_REP * SLOTS];   // class sums, [rep][class][col4]
__device__ int          g_class_counts[N_CLASSES];
__device__ float4       g_T4[D_DIM / 4];        // column totals
__device__ double       g_ps;                   // sum_c ||S_c||^2
__device__ unsigned int g_ticket;

__device__ __forceinline__ void red_add_v4(float4* addr, float4 v) {
    asm volatile("red.global.add.v4.f32 [%0], {%1,%2,%3,%4};"
                 :: "l"(addr), "f"(v.x), "f"(v.y), "f"(v.z), "f"(v.w)
                 : "memory");
}

// ---------------------------------------------------------------------------
// Kernel 1: warp-per-row normalize + scatter (vector REDs, no barriers).
// 8 warps/block, 1024 blocks. Lane owns 8 consecutive dims (2 x float4).
// ---------------------------------------------------------------------------
__global__ void accum_kernel(const int* __restrict__ y_true,
                             const float4* __restrict__ y_pred4) {
    const int warp = threadIdx.x >> 5;
    const int lane = threadIdx.x & 31;
    const int row  = blockIdx.x * 8 + warp;
    const int rep  = blockIdx.x & (R_REP - 1);

    const int c = __ldg(&y_true[row]);
    float4 a = y_pred4[row * 64 + lane * 2];
    float4 b = y_pred4[row * 64 + lane * 2 + 1];

    float sq = a.x*a.x + a.y*a.y + a.z*a.z + a.w*a.w
             + b.x*b.x + b.y*b.y + b.z*b.z + b.w*b.w;
    #pragma unroll
    for (int o = 16; o > 0; o >>= 1)
        sq += __shfl_xor_sync(0xffffffffu, sq, o);

    const float inv = (sq > 0.0f) ? rsqrtf(sq) : 0.0f;
    a.x *= inv; a.y *= inv; a.z *= inv; a.w *= inv;
    b.x *= inv; b.y *= inv; b.z *= inv; b.w *= inv;

    float4* dst = &g_cs4[(rep * N_CLASSES + c) * 64 + lane * 2];
    red_add_v4(dst,     a);
    red_add_v4(dst + 1, b);
    if (lane == 0) atomicAdd(&g_class_counts[c], 1);
}

// ---------------------------------------------------------------------------
// Kernel 2: reduce + finalize (ticket-fused). 128 blocks x 256 threads.
// Thread owns ONE (class, col4) slot: slot = bid*256 + t. Reads the 4 replicas
// at stride SLOTS (each read fully coalesced: consecutive threads ->
// consecutive float4), zeroes them, squares into ps, REDs S into g_T4[col].
// Last block computes total = ||T||^2, n_pos, and the final scalar.
// ---------------------------------------------------------------------------
__global__ void reduce_final_kernel(float* __restrict__ out) {
    const int t    = threadIdx.x;
    const int slot = blockIdx.x * 256 + t;        // 0..32767
    const int col  = slot & 63;                   // float4 column slot

    float4 S = make_float4(0.f, 0.f, 0.f, 0.f);
    #pragma unroll
    for (int r = 0; r < R_REP; r++) {
        const int idx = r * SLOTS + slot;
        float4 v = g_cs4[idx];
        g_cs4[idx] = make_float4(0.f, 0.f, 0.f, 0.f);   // replay hygiene
        S.x += v.x; S.y += v.y; S.z += v.z; S.w += v.w;
    }

    double ps = (double)S.x * S.x + (double)S.y * S.y
              + (double)S.z * S.z + (double)S.w * S.w;

    red_add_v4(&g_T4[col], S);                    // 512 adds/address, spread

    // Block-reduce ps (fp64), one atomic per block.
    __shared__ double shP[256];
    shP[t] = ps;
    __syncthreads();
    #pragma unroll
    for (int off = 128; off > 0; off >>= 1) {
        if (t < off) shP[t] += shP[t + off];
        __syncthreads();
    }

    __shared__ int isLast;
    if (t == 0) {
        atomicAdd(&g_ps, shP[0]);
        __threadfence();
        unsigned tk = atomicAdd(&g_ticket, 1u);
        isLast = (tk == gridDim.x - 1) ? 1 : 0;
    }
    __syncthreads();

    if (isLast) {
        __threadfence();   // order: see all blocks' g_T4 / g_ps updates

        // total_sum partial: threads 0..63 own one float4 of T.
        double tot = 0.0;
        if (t < 64) {
            float4 T = g_T4[t];
            g_T4[t] = make_float4(0.f, 0.f, 0.f, 0.f);  // replay hygiene
            tot = (double)T.x * T.x + (double)T.y * T.y
                + (double)T.z * T.z + (double)T.w * T.w;
        }

        long long c0 = g_class_counts[t];        g_class_counts[t] = 0;
        long long c1 = g_class_counts[t + 256];  g_class_counts[t + 256] = 0;
        long long np = c0 * c0 + c1 * c1;

        __shared__ double    shT[256];
        __shared__ long long shN[256];
        shT[t] = tot; shN[t] = np;
        __syncthreads();
        #pragma unroll
        for (int off = 128; off > 0; off >>= 1) {
            if (t < off) { shT[t] += shT[t + off]; shN[t] += shN[t + off]; }
            __syncthreads();
        }

        if (t == 0) {
            double pos_sum = atomicAdd(&g_ps, 0.0);
            g_ps = 0.0; g_ticket = 0u;            // replay hygiene
            double total_sum = shT[0];
            double n_pos   = (double)shN[0];
            double n_neg   = (double)B_ROWS * (double)B_ROWS - n_pos;
            double neg_sum = total_sum - pos_sum;
            double pos_d   = pos_sum / n_pos;
            double neg_d   = (n_neg > 0.0) ? (neg_sum / n_neg) : 0.0;
            double r = pos_d - neg_d + ALPHA;
            out[0] = (float)(r > 0.0 ? r : 0.0);
        }
    }
}

// ---------------------------------------------------------------------------
extern "C" void kernel_launch(void* const* d_in, const int* in_sizes, int n_in,
                              void* d_out, int out_size) {
    const int*   y_true;
    const float* y_pred;
    if (in_sizes[0] == B_ROWS) {
        y_true = (const int*)d_in[0];
        y_pred = (const float*)d_in[1];
    } else {
        y_true = (const int*)d_in[1];
        y_pred = (const float*)d_in[0];
    }
    float* out = (float*)d_out;

    accum_kernel<<<B_ROWS / 8, 256>>>(y_true, (const float4*)y_pred);
    reduce_final_kernel<<<SLOTS / 256, 256>>>(out);
}

// round 5
// speedup vs baseline: 1.2390x; 1.2390x over previous
#include <cuda_runtime.h>
#include <cuda_bf16.h>
#include <math.h>
#include <stdint.h>

#define B_ROWS    8192
#define D_DIM     256
#define N_CLASSES 512
#define ALPHA     0.1
#define CPB       4                    // classes per block
#define NBLK      (N_CLASSES / CPB)    // 128 blocks
#define LIST_CAP  2048                 // >> expected 16 rows/class; safety cap

// Column totals, padded to one 128B line per float4 so the per-address RED
// chains (128 ops each) land on 64 distinct lines.
struct Pad128 { float4 v; float4 pad[7]; };
__device__ Pad128             g_T4p[D_DIM / 4];
__device__ double             g_ps;      // sum_c ||S_c||^2
__device__ unsigned long long g_np;      // sum_c count_c^2
__device__ unsigned int       g_ticket;

__device__ __forceinline__ void red_add_v4(float4* addr, float4 v) {
    asm volatile("red.global.add.v4.f32 [%0], {%1,%2,%3,%4};"
                 :: "l"(addr), "f"(v.x), "f"(v.y), "f"(v.z), "f"(v.w)
                 : "memory");
}

// ---------------------------------------------------------------------------
// ONE kernel. Block b owns classes [4b, 4b+4).
//  1) scan labels (32KB, L2-resident) -> per-class row lists in smem
//  2) 2 warps per class gather + normalize rows, accumulate S in registers
//  3) combine warps in smem; compute ps, T-partials, np locally
//  4) tiny REDs; ticket; last block runs the scalar epilogue
// ---------------------------------------------------------------------------
__global__ __launch_bounds__(256, 1)
void triplet_kernel(const int* __restrict__ y_true,
                    const float4* __restrict__ yp,
                    float* __restrict__ out) {
    __shared__ uint16_t list[CPB][LIST_CAP];   // 16 KB
    __shared__ int      cnt[CPB];
    __shared__ float4   wsum[8][64];           // 8 KB: per-warp partial sums
    __shared__ float4   sclass[CPB][64];       // 4 KB: final S per class
    __shared__ double   shP[256];
    __shared__ int      isLast;

    const int t     = threadIdx.x;
    const int w     = t >> 5;
    const int lane  = t & 31;
    const int cbase = blockIdx.x * CPB;

    if (t < CPB) cnt[t] = 0;
    __syncthreads();

    // ---- 1) label scan: coalesced, every block reads the same 32KB ----
    #pragma unroll
    for (int i = 0; i < B_ROWS / 256; i++) {
        const int row = t + i * 256;
        const unsigned k = (unsigned)(__ldg(&y_true[row]) - cbase);
        if (k < CPB) {
            int pos = atomicAdd(&cnt[k], 1);
            if (pos < LIST_CAP) list[k][pos] = (uint16_t)row;
        }
    }
    __syncthreads();

    // ---- 2) gather rows: warp w handles class (w>>1), parity (w&1) ----
    // Lane owns dims [lane*4, lane*4+4) and [128+lane*4, ...): contiguous
    // LDG.128s (full 32B sectors). Software-pipelined one row ahead.
    const int k   = w >> 1;
    const int par = w & 1;
    const int n   = min(cnt[k], LIST_CAP);

    float4 A = make_float4(0.f, 0.f, 0.f, 0.f);
    float4 Bv = make_float4(0.f, 0.f, 0.f, 0.f);

    int j = par;
    float4 a, b;
    if (j < n) {
        const int r = list[k][j];
        a = yp[r * 64 + lane];
        b = yp[r * 64 + 32 + lane];
    }
    while (j < n) {
        const int jn = j + 2;
        float4 a2, b2;
        if (jn < n) {                       // prefetch next row
            const int r2 = list[k][jn];
            a2 = yp[r2 * 64 + lane];
            b2 = yp[r2 * 64 + 32 + lane];
        }
        float sq = a.x*a.x + a.y*a.y + a.z*a.z + a.w*a.w
                 + b.x*b.x + b.y*b.y + b.z*b.z + b.w*b.w;
        #pragma unroll
        for (int o = 16; o > 0; o >>= 1)
            sq += __shfl_xor_sync(0xffffffffu, sq, o);
        const float inv = (sq > 0.0f) ? rsqrtf(sq) : 0.0f;
        A.x += a.x * inv; A.y += a.y * inv; A.z += a.z * inv; A.w += a.w * inv;
        Bv.x += b.x * inv; Bv.y += b.y * inv; Bv.z += b.z * inv; Bv.w += b.w * inv;
        a = a2; b = b2; j = jn;
    }
    wsum[w][lane]      = A;
    wsum[w][32 + lane] = Bv;
    __syncthreads();

    // ---- 3) combine: thread t -> class g = t>>6, col4 slot s = t&63 ----
    const int g = t >> 6, s = t & 63;
    float4 x0 = wsum[2 * g][s], x1 = wsum[2 * g + 1][s];
    float4 S = make_float4(x0.x + x1.x, x0.y + x1.y, x0.z + x1.z, x0.w + x1.w);
    sclass[g][s] = S;

    double ps = (double)S.x * S.x + (double)S.y * S.y
              + (double)S.z * S.z + (double)S.w * S.w;
    shP[t] = ps;
    __syncthreads();
    #pragma unroll
    for (int off = 128; off > 0; off >>= 1) {
        if (t < off) shP[t] += shP[t + off];
        __syncthreads();
    }

    // T-partials: 64 REDs per block, one 128B line each (128 ops/addr total)
    if (t < 64) {
        float4 T = sclass[0][t];
        float4 c1 = sclass[1][t], c2 = sclass[2][t], c3 = sclass[3][t];
        T.x += c1.x + c2.x + c3.x;  T.y += c1.y + c2.y + c3.y;
        T.z += c1.z + c2.z + c3.z;  T.w += c1.w + c2.w + c3.w;
        red_add_v4(&g_T4p[t].v, T);
    }
    if (t == 0) {
        long long np = 0;
        #pragma unroll
        for (int kk = 0; kk < CPB; kk++) {
            long long c = cnt[kk];
            np += c * c;
        }
        atomicAdd(&g_np, (unsigned long long)np);
        atomicAdd(&g_ps, shP[0]);
    }
    __threadfence();
    __syncthreads();

    // ---- 4) ticket + epilogue ----
    if (t == 0) {
        unsigned tk = atomicAdd(&g_ticket, 1u);
        isLast = (tk == gridDim.x - 1) ? 1 : 0;
    }
    __syncthreads();

    if (isLast) {
        __threadfence();
        double tot = 0.0;
        if (t < 64) {
            float4 T = g_T4p[t].v;
            g_T4p[t].v = make_float4(0.f, 0.f, 0.f, 0.f);   // replay hygiene
            tot = (double)T.x * T.x + (double)T.y * T.y
                + (double)T.z * T.z + (double)T.w * T.w;
        }
        shP[t] = tot;
        __syncthreads();
        #pragma unroll
        for (int off = 128; off > 0; off >>= 1) {
            if (t < off) shP[t] += shP[t + off];
            __syncthreads();
        }
        if (t == 0) {
            double pos_sum   = atomicAdd(&g_ps, 0.0);
            double n_pos     = (double)atomicAdd(&g_np, 0ull);
            g_ps = 0.0; g_np = 0ull; g_ticket = 0u;          // replay hygiene
            double total_sum = shP[0];
            double n_neg   = (double)B_ROWS * (double)B_ROWS - n_pos;
            double neg_sum = total_sum - pos_sum;
            double pos_d   = pos_sum / n_pos;
            double neg_d   = (n_neg > 0.0) ? (neg_sum / n_neg) : 0.0;
            double r = pos_d - neg_d + ALPHA;
            out[0] = (float)(r > 0.0 ? r : 0.0);
        }
    }
}

// ---------------------------------------------------------------------------
extern "C" void kernel_launch(void* const* d_in, const int* in_sizes, int n_in,
                              void* d_out, int out_size) {
    const int*   y_true;
    const float* y_pred;
    if (in_sizes[0] == B_ROWS) {
        y_true = (const int*)d_in[0];
        y_pred = (const float*)d_in[1];
    } else {
        y_true = (const int*)d_in[1];
        y_pred = (const float*)d_in[0];
    }
    float* out = (float*)d_out;

    triplet_kernel<<<NBLK, 256>>>(y_true, (const float4*)y_pred, out);
}

// round 6
// speedup vs baseline: 1.4485x; 1.1691x over previous
#include <cuda_runtime.h>
#include <cuda_bf16.h>
#include <math.h>
#include <stdint.h>

#define B_ROWS    8192
#define D_DIM     256
#define N_CLASSES 512
#define ALPHA     0.1
#define LIST_CAP  96        // max rows/class; Poisson(16) max ~40, big margin
#define NWARP     16        // warps per block (512 threads)

// Column totals, one 128B line per float4 slot (REDs per address form a
// 512-deep chain at ~0.85 cyc/op -- negligible when lines are distinct).
struct Pad128 { float4 v; float4 pad[7]; };
__device__ Pad128             g_T4p[D_DIM / 4];
__device__ double             g_ps;      // sum_c ||S_c||^2
__device__ unsigned long long g_np;      // sum_c count_c^2
__device__ unsigned int       g_ticket;

__device__ __forceinline__ void red_add_v4(float4* addr, float4 v) {
    asm volatile("red.global.add.v4.f32 [%0], {%1,%2,%3,%4};"
                 :: "l"(addr), "f"(v.x), "f"(v.y), "f"(v.z), "f"(v.w)
                 : "memory");
}

// ---------------------------------------------------------------------------
// ONE kernel, one class per block. 512 blocks x 512 threads.
//  1) scan labels (int4, L2-resident) -> this class's row list in smem
//  2) one row per warp (parallel): load 1KB coalesced, normalize, accumulate
//  3) combine 16 warp-partials; local ps, np; 64 padded v4-REDs for T
//  4) ticket; last block computes ||T||^2 and the final scalar
// ---------------------------------------------------------------------------
__global__ __launch_bounds__(512)
void triplet_kernel(const int4* __restrict__ y4,
                    const float4* __restrict__ yp,
                    float* __restrict__ out) {
    __shared__ uint16_t list[LIST_CAP];
    __shared__ int      cnt;
    __shared__ float4   wsum[NWARP][64];     // 16 KB
    __shared__ double   shP[64];
    __shared__ int      isLast;

    const int t    = threadIdx.x;
    const int w    = t >> 5;
    const int lane = t & 31;
    const int c    = blockIdx.x;             // my class

    if (t == 0) cnt = 0;
    __syncthreads();

    // ---- 1) label scan: 4 x int4 per thread (16 labels) ----
    #pragma unroll
    for (int i = 0; i < (B_ROWS / 4) / 512; i++) {
        const int q = t + i * 512;           // int4 index
        const int4 L = y4[q];
        if (L.x == c) { int p = atomicAdd(&cnt, 1); if (p < LIST_CAP) list[p] = (uint16_t)(q * 4 + 0); }
        if (L.y == c) { int p = atomicAdd(&cnt, 1); if (p < LIST_CAP) list[p] = (uint16_t)(q * 4 + 1); }
        if (L.z == c) { int p = atomicAdd(&cnt, 1); if (p < LIST_CAP) list[p] = (uint16_t)(q * 4 + 2); }
        if (L.w == c) { int p = atomicAdd(&cnt, 1); if (p < LIST_CAP) list[p] = (uint16_t)(q * 4 + 3); }
    }
    __syncthreads();

    // ---- 2) gather: warp w handles rows w, w+16, ... (typically one) ----
    const int n = min(cnt, LIST_CAP);
    float4 A = make_float4(0.f, 0.f, 0.f, 0.f);
    float4 Bv = make_float4(0.f, 0.f, 0.f, 0.f);
    for (int j = w; j < n; j += NWARP) {
        const int r = list[j];
        float4 a = yp[r * 64 + lane];        // dims [lane*4, lane*4+4)
        float4 b = yp[r * 64 + 32 + lane];   // dims [128+lane*4, ...)
        float sq = a.x*a.x + a.y*a.y + a.z*a.z + a.w*a.w
                 + b.x*b.x + b.y*b.y + b.z*b.z + b.w*b.w;
        #pragma unroll
        for (int o = 16; o > 0; o >>= 1)
            sq += __shfl_xor_sync(0xffffffffu, sq, o);
        const float inv = (sq > 0.0f) ? rsqrtf(sq) : 0.0f;
        A.x += a.x * inv; A.y += a.y * inv; A.z += a.z * inv; A.w += a.w * inv;
        Bv.x += b.x * inv; Bv.y += b.y * inv; Bv.z += b.z * inv; Bv.w += b.w * inv;
    }
    wsum[w][lane]      = A;
    wsum[w][32 + lane] = Bv;
    __syncthreads();

    // ---- 3) combine 16 warp-partials; threads 0..63 own one float4 slot ----
    if (t < 64) {
        float4 S = wsum[0][t];
        #pragma unroll
        for (int i = 1; i < NWARP; i++) {
            float4 v = wsum[i][t];
            S.x += v.x; S.y += v.y; S.z += v.z; S.w += v.w;
        }
        red_add_v4(&g_T4p[t].v, S);          // T column partial
        shP[t] = (double)S.x * S.x + (double)S.y * S.y
               + (double)S.z * S.z + (double)S.w * S.w;
    }
    __syncthreads();
    if (t < 32) shP[t] += shP[t + 32];
    __syncwarp(0xffffffffu);
    if (t < 32) {
        double p = shP[t];
        #pragma unroll
        for (int o = 16; o > 0; o >>= 1)
            p += __shfl_xor_sync(0xffffffffu, p, o);
        if (t == 0) {
            atomicAdd(&g_ps, p);
            long long nn = n;
            atomicAdd(&g_np, (unsigned long long)(nn * nn));
        }
    }
    __threadfence();
    __syncthreads();

    // ---- 4) ticket + epilogue ----
    if (t == 0) {
        unsigned tk = atomicAdd(&g_ticket, 1u);
        isLast = (tk == gridDim.x - 1) ? 1 : 0;
    }
    __syncthreads();

    if (isLast) {
        __threadfence();
        if (t < 64) {
            float4 T = g_T4p[t].v;
            g_T4p[t].v = make_float4(0.f, 0.f, 0.f, 0.f);    // replay hygiene
            shP[t] = (double)T.x * T.x + (double)T.y * T.y
                   + (double)T.z * T.z + (double)T.w * T.w;
        }
        __syncthreads();
        if (t < 32) shP[t] += shP[t + 32];
        __syncwarp(0xffffffffu);
        if (t < 32) {
            double p = shP[t];
            #pragma unroll
            for (int o = 16; o > 0; o >>= 1)
                p += __shfl_xor_sync(0xffffffffu, p, o);
            if (t == 0) {
                double pos_sum   = atomicAdd(&g_ps, 0.0);
                double n_pos     = (double)atomicAdd(&g_np, 0ull);
                g_ps = 0.0; g_np = 0ull; g_ticket = 0u;      // replay hygiene
                double total_sum = p;
                double n_neg   = (double)B_ROWS * (double)B_ROWS - n_pos;
                double neg_sum = total_sum - pos_sum;
                double pos_d   = pos_sum / n_pos;
                double neg_d   = (n_neg > 0.0) ? (neg_sum / n_neg) : 0.0;
                double r = pos_d - neg_d + ALPHA;
                out[0] = (float)(r > 0.0 ? r : 0.0);
            }
        }
    }
}

// ---------------------------------------------------------------------------
extern "C" void kernel_launch(void* const* d_in, const int* in_sizes, int n_in,
                              void* d_out, int out_size) {
    const int*   y_true;
    const float* y_pred;
    if (in_sizes[0] == B_ROWS) {
        y_true = (const int*)d_in[0];
        y_pred = (const float*)d_in[1];
    } else {
        y_true = (const int*)d_in[1];
        y_pred = (const float*)d_in[0];
    }
    float* out = (float*)d_out;

    triplet_kernel<<<N_CLASSES, 512>>>((const int4*)y_true,
                                       (const float4*)y_pred, out);
}

// round 7
// speedup vs baseline: 1.4775x; 1.0200x over previous
#include <cuda_runtime.h>
#include <cuda_bf16.h>
#include <math.h>
#include <stdint.h>

#define B_ROWS    8192
#define D_DIM     256
#define N_CLASSES 512
#define ALPHA     0.1
#define LIST_CAP  96        // max rows/class; Poisson(16) max ~40, big margin
#define NWARP     16        // warps per block (512 threads)

// Column totals, one 128B line per float4 slot.
struct Pad128 { float4 v; float4 pad[7]; };
__device__ Pad128             g_T4p[D_DIM / 4];
__device__ double             g_ps;      // sum_c ||S_c||^2
__device__ unsigned long long g_np;      // sum_c count_c^2
__device__ unsigned int       g_ticket;

__device__ __forceinline__ void red_add_v4(float4* addr, float4 v) {
    asm volatile("red.global.add.v4.f32 [%0], {%1,%2,%3,%4};"
                 :: "l"(addr), "f"(v.x), "f"(v.y), "f"(v.z), "f"(v.w)
                 : "memory");
}

// Ticket with acq_rel semantics: release makes this block's prior (syncthreads-
// ordered) device-scope REDs visible; acquire lets the last block see all
// other blocks' REDs. NO MEMBAR.GPU / CCTL.IVALL (L1 flush) anywhere.
__device__ __forceinline__ unsigned ticket_acq_rel(unsigned int* a) {
    unsigned old;
    asm volatile("atom.add.acq_rel.gpu.global.u32 %0, [%1], 1;"
                 : "=r"(old) : "l"(a) : "memory");
    return old;
}

__device__ __forceinline__ float4 ldcg4(const float4* p) {
    float4 v;
    asm volatile("ld.global.cg.v4.f32 {%0,%1,%2,%3}, [%4];"
                 : "=f"(v.x), "=f"(v.y), "=f"(v.z), "=f"(v.w) : "l"(p));
    return v;
}

// ---------------------------------------------------------------------------
// ONE kernel, one class per block. 512 blocks x 512 threads.
// ---------------------------------------------------------------------------
__global__ __launch_bounds__(512)
void triplet_kernel(const int4* __restrict__ y4,
                    const float4* __restrict__ yp,
                    float* __restrict__ out) {
    __shared__ uint16_t list[LIST_CAP];
    __shared__ int      cnt;
    __shared__ float4   wsum[NWARP][64];     // 16 KB
    __shared__ double   shP[64];
    __shared__ int      isLast;

    const int t    = threadIdx.x;
    const int w    = t >> 5;
    const int lane = t & 31;
    const int c    = blockIdx.x;             // my class

    if (t == 0) cnt = 0;
    __syncthreads();

    // ---- 1) label scan: 4 x int4 per thread (16 labels), L2-resident ----
    #pragma unroll
    for (int i = 0; i < (B_ROWS / 4) / 512; i++) {
        const int q = t + i * 512;           // int4 index
        const int4 L = y4[q];
        if (L.x == c) { int p = atomicAdd(&cnt, 1); if (p < LIST_CAP) list[p] = (uint16_t)(q * 4 + 0); }
        if (L.y == c) { int p = atomicAdd(&cnt, 1); if (p < LIST_CAP) list[p] = (uint16_t)(q * 4 + 1); }
        if (L.z == c) { int p = atomicAdd(&cnt, 1); if (p < LIST_CAP) list[p] = (uint16_t)(q * 4 + 2); }
        if (L.w == c) { int p = atomicAdd(&cnt, 1); if (p < LIST_CAP) list[p] = (uint16_t)(q * 4 + 3); }
    }
    __syncthreads();

    // ---- 2) gather: warp w handles rows w, w+16, ... (typically one) ----
    const int n = min(cnt, LIST_CAP);
    float4 A = make_float4(0.f, 0.f, 0.f, 0.f);
    float4 Bv = make_float4(0.f, 0.f, 0.f, 0.f);
    for (int j = w; j < n; j += NWARP) {
        const int r = list[j];
        float4 a = __ldcs(&yp[r * 64 + lane]);       // streaming: read-once
        float4 b = __ldcs(&yp[r * 64 + 32 + lane]);
        float sq = a.x*a.x + a.y*a.y + a.z*a.z + a.w*a.w
                 + b.x*b.x + b.y*b.y + b.z*b.z + b.w*b.w;
        #pragma unroll
        for (int o = 16; o > 0; o >>= 1)
            sq += __shfl_xor_sync(0xffffffffu, sq, o);
        const float inv = (sq > 0.0f) ? rsqrtf(sq) : 0.0f;
        A.x += a.x * inv; A.y += a.y * inv; A.z += a.z * inv; A.w += a.w * inv;
        Bv.x += b.x * inv; Bv.y += b.y * inv; Bv.z += b.z * inv; Bv.w += b.w * inv;
    }
    wsum[w][lane]      = A;
    wsum[w][32 + lane] = Bv;
    __syncthreads();

    // ---- 3) combine 16 warp-partials; threads 0..63 own one float4 slot ----
    if (t < 64) {
        float4 S = wsum[0][t];
        #pragma unroll
        for (int i = 1; i < NWARP; i++) {
            float4 v = wsum[i][t];
            S.x += v.x; S.y += v.y; S.z += v.z; S.w += v.w;
        }
        red_add_v4(&g_T4p[t].v, S);          // T column partial (device RED)
        shP[t] = (double)S.x * S.x + (double)S.y * S.y
               + (double)S.z * S.z + (double)S.w * S.w;
    }
    __syncthreads();
    if (t < 32) {
        double p = shP[t] + shP[t + 32];
        #pragma unroll
        for (int o = 16; o > 0; o >>= 1)
            p += __shfl_xor_sync(0xffffffffu, p, o);
        if (t == 0) {
            atomicAdd(&g_ps, p);
            long long nn = n;
            atomicAdd(&g_np, (unsigned long long)(nn * nn));
        }
    }
    __syncthreads();                          // all REDs issued before release

    // ---- 4) acq_rel ticket + epilogue (no membar, no L1 flush) ----
    if (t == 0)
        isLast = (ticket_acq_rel(&g_ticket) == gridDim.x - 1) ? 1 : 0;
    __syncthreads();

    if (isLast) {
        if (t < 64) {
            float4 T = ldcg4(&g_T4p[t].v);    // L2 read (where REDs landed)
            g_T4p[t].v = make_float4(0.f, 0.f, 0.f, 0.f);   // replay hygiene
            shP[t] = (double)T.x * T.x + (double)T.y * T.y
                   + (double)T.z * T.z + (double)T.w * T.w;
        }
        __syncthreads();
        if (t < 32) {
            double p = shP[t] + shP[t + 32];
            #pragma unroll
            for (int o = 16; o > 0; o >>= 1)
                p += __shfl_xor_sync(0xffffffffu, p, o);
            if (t == 0) {
                double pos_sum   = atomicAdd(&g_ps, 0.0);
                double n_pos     = (double)atomicAdd(&g_np, 0ull);
                g_ps = 0.0; g_np = 0ull; g_ticket = 0u;      // replay hygiene
                double total_sum = p;
                double n_neg   = (double)B_ROWS * (double)B_ROWS - n_pos;
                double neg_sum = total_sum - pos_sum;
                double pos_d   = pos_sum / n_pos;
                double neg_d   = (n_neg > 0.0) ? (neg_sum / n_neg) : 0.0;
                double r = pos_d - neg_d + ALPHA;
                out[0] = (float)(r > 0.0 ? r : 0.0);
            }
        }
    }
}

// ---------------------------------------------------------------------------
extern "C" void kernel_launch(void* const* d_in, const int* in_sizes, int n_in,
                              void* d_out, int out_size) {
    const int*   y_true;
    const float* y_pred;
    if (in_sizes[0] == B_ROWS) {
        y_true = (const int*)d_in[0];
        y_pred = (const float*)d_in[1];
    } else {
        y_true = (const int*)d_in[1];
        y_pred = (const float*)d_in[0];
    }
    float* out = (float*)d_out;

    triplet_kernel<<<N_CLASSES, 512>>>((const int4*)y_true,
                                       (const float4*)y_pred, out);
}